// round 12
// baseline (speedup 1.0000x reference)
#include <cuda_runtime.h>
#include <math.h>

#define BATCH 4
#define SEQL  2048
#define DIM   768
#define NST   16
#define BL    (BATCH*SEQL)
#define NCH   32
#define CL    (SEQL/NCH)   // 64
#define HCL   (CL/2)       // 32 (u staged in halves)

#define TL 64              // proj tile == chunk
#define KC 32
#define LOG2E 1.4426950408889634f

typedef unsigned long long u64;

// scratch (static device globals — no runtime allocation)
__device__ float g_delta[BL];
__device__ float g_sdelta[BATCH*NCH];
__device__ float g_Bt[BL*NST];   // [pos][n]
__device__ float g_Ct[BL*NST];   // [pos][n]
__device__ float g_xend [BATCH*DIM*NCH*NST];
__device__ float g_xinit[BATCH*DIM*NCH*NST];

__device__ __forceinline__ float ex2f(float x) {
    float y;
    asm("ex2.approx.ftz.f32 %0, %1;" : "=f"(y) : "f"(x));
    return y;
}
__device__ __forceinline__ u64 pack2(float lo, float hi) {
    u64 r; asm("mov.b64 %0, {%1, %2};" : "=l"(r) : "f"(lo), "f"(hi)); return r;
}
__device__ __forceinline__ float2 unpack2(u64 v) {
    float2 f; asm("mov.b64 {%0, %1}, %2;" : "=f"(f.x), "=f"(f.y) : "l"(v)); return f;
}
__device__ __forceinline__ u64 fma2(u64 a, u64 b, u64 c) {
    u64 r; asm("fma.rn.f32x2 %0, %1, %2, %3;" : "=l"(r) : "l"(a), "l"(b), "l"(c)); return r;
}
__device__ __forceinline__ u64 mul2(u64 a, u64 b) {
    u64 r; asm("mul.rn.f32x2 %0, %1, %2;" : "=l"(r) : "l"(a), "l"(b)); return r;
}

// ---- kernel 1: proj + fused delta/softplus + chunk delta-sums ---------------
__global__ void proj_kernel(const float* __restrict__ u,
                            const float* __restrict__ W_B,
                            const float* __restrict__ W_C,
                            const float* __restrict__ q_delta,
                            const float* __restrict__ p_delta) {
    __shared__ __align__(16) float Us[KC*68];
    __shared__ __align__(16) float Ws[KC*36];
    __shared__ __align__(16) float Bo[TL*NST];
    __shared__ __align__(16) float Co[TL*NST];
    int t  = threadIdx.x;       // 128 threads
    int tx = t & 15;
    int ty = t >> 4;
    int blb = blockIdx.x * TL;

    float acc[4][4];
    float dacc[4] = {0.f, 0.f, 0.f, 0.f};
#pragma unroll
    for (int a = 0; a < 4; a++)
#pragma unroll
        for (int c = 0; c < 4; c++) acc[a][c] = 0.f;

    for (int dc = 0; dc < DIM; dc += KC) {
#pragma unroll
        for (int it = 0; it < (TL*KC)/128; it++) {
            int idx = t + it*128;
            int k = idx & 31, p = idx >> 5;
            Us[k*68 + p] = u[(size_t)(blb + p)*DIM + dc + k];
        }
#pragma unroll
        for (int it = 0; it < (32*KC)/128; it++) {
            int idx = t + it*128;
            int k = idx & 31, j = idx >> 5;
            const float* wr = (j < 16) ? (W_B + j*DIM) : (W_C + (j-16)*DIM);
            Ws[k*36 + j] = wr[dc + k];
        }
        if (t < 32) Ws[t*36 + 32] = q_delta[dc + t];
        __syncthreads();
#pragma unroll
        for (int k = 0; k < KC; k++) {
            float4 u4 = *(const float4*)(Us + k*68 + tx*4);
            float4 w4 = *(const float4*)(Ws + k*36 + ty*4);
            float us[4] = {u4.x, u4.y, u4.z, u4.w};
            float ws4[4] = {w4.x, w4.y, w4.z, w4.w};
#pragma unroll
            for (int a = 0; a < 4; a++)
#pragma unroll
                for (int c = 0; c < 4; c++)
                    acc[a][c] = fmaf(ws4[a], us[c], acc[a][c]);
            if (ty == 0) {
                float qk = Ws[k*36 + 32];
#pragma unroll
                for (int c = 0; c < 4; c++)
                    dacc[c] = fmaf(qk, us[c], dacc[c]);
            }
        }
        __syncthreads();
    }
    if (ty == 0) {
        float p0 = p_delta[0];
        float s = 0.f;
#pragma unroll
        for (int c = 0; c < 4; c++) {
            float z = dacc[c] + p0;
            float sp = (z > 20.f) ? z : log1pf(__expf(z));
            g_delta[blb + tx*4 + c] = sp;
            s += sp;
        }
#pragma unroll
        for (int o = 8; o; o >>= 1) s += __shfl_xor_sync(0xffffu, s, o);
        if (tx == 0) g_sdelta[blockIdx.x] = s;
    }
#pragma unroll
    for (int a = 0; a < 4; a++) {
        int j = ty*4 + a;
        float* o = (j < 16) ? Bo : Co;
        int jj = j & 15;
#pragma unroll
        for (int c = 0; c < 4; c++)
            o[(tx*4 + c)*NST + jj] = acc[a][c];
    }
    __syncthreads();
#pragma unroll
    for (int it = 0; it < (TL*NST)/(128*4); it++) {
        int i = (t + it*128)*4;
        *(float4*)(g_Bt + (size_t)blb*NST + i) = *(const float4*)(Bo + i);
        *(float4*)(g_Ct + (size_t)blb*NST + i) = *(const float4*)(Co + i);
    }
}

// ---- kernel 2: local chunk scans (x0 = 0) -> x_end, packed f32x2 ------------
__global__ void __launch_bounds__(128, 6) scan_init_kernel(const float* __restrict__ u,
                                                           const float* __restrict__ A) {
    __shared__ float ds[CL];
    __shared__ __align__(16) float Bs[CL*NST];
    __shared__ __align__(16) float Uss[HCL*128];   // half tile
    int t = threadIdx.x;
    int b = blockIdx.z, c = blockIdx.y;
    int d0 = blockIdx.x * 128;
    int d = d0 + t;
    int pos0 = b*SEQL + c*CL;

    if (t < CL) ds[t] = g_delta[pos0 + t];
#pragma unroll
    for (int i = t; i < CL*NST/4; i += 128)
        *(float4*)(Bs + i*4) = *(const float4*)(g_Bt + (size_t)pos0*NST + i*4);

    float A2[NST];
#pragma unroll
    for (int k = 0; k < 4; k++) {
        float4 a4 = *(const float4*)(A + d*NST + k*4);
        A2[k*4+0] = a4.x*LOG2E; A2[k*4+1] = a4.y*LOG2E;
        A2[k*4+2] = a4.z*LOG2E; A2[k*4+3] = a4.w*LOG2E;
    }
    u64 xp[8];
#pragma unroll
    for (int q = 0; q < 8; q++) xp[q] = 0ull;

#pragma unroll
    for (int h = 0; h < 2; h++) {
        // stage u half-tile [HCL][128]
#pragma unroll
        for (int i = t; i < HCL*32; i += 128) {
            int row = i >> 5, col = i & 31;
            *(float4*)(Uss + row*128 + col*4) =
                *(const float4*)(u + (size_t)(pos0 + h*HCL + row)*DIM + d0 + col*4);
        }
        __syncthreads();
#pragma unroll 4
        for (int ll = 0; ll < HCL; ll++) {
            int l = h*HCL + ll;
            float dl = ds[l];
            float du = dl * Uss[ll*128 + t];
            u64 dup = pack2(du, du);
            const ulonglong2* bp = (const ulonglong2*)(Bs + l*NST);
#pragma unroll
            for (int k = 0; k < 4; k++) {
                float e0 = ex2f(dl*A2[k*4+0]);
                float e1 = ex2f(dl*A2[k*4+1]);
                float e2 = ex2f(dl*A2[k*4+2]);
                float e3 = ex2f(dl*A2[k*4+3]);
                u64 a01 = pack2(e0, e1), a23 = pack2(e2, e3);
                ulonglong2 bv = bp[k];
                xp[k*2+0] = fma2(a01, xp[k*2+0], mul2(dup, bv.x));
                xp[k*2+1] = fma2(a23, xp[k*2+1], mul2(dup, bv.y));
            }
        }
        __syncthreads();
    }
    ulonglong2* xe = (ulonglong2*)(g_xend + (((size_t)b*DIM + d)*NCH + c)*NST);
#pragma unroll
    for (int q = 0; q < 4; q++)
        xe[q] = make_ulonglong2(xp[q*2], xp[q*2+1]);
}

// ---- kernel 3: serial chain over chunks -> x_init ---------------------------
__global__ void chain_kernel(const float* __restrict__ A) {
    int t = blockIdx.x * blockDim.x + threadIdx.x;
    int n = t & 15;
    int bd = t >> 4;
    int b = bd / DIM;
    int d = bd - b*DIM;
    float A2 = A[d*NST + n] * LOG2E;
    float x = 0.f;
#pragma unroll
    for (int c = 0; c < NCH; c++) {
        size_t idx = ((size_t)bd*NCH + c)*NST + n;
        g_xinit[idx] = x;
        float P = ex2f(A2 * g_sdelta[b*NCH + c]);
        x = fmaf(P, x, g_xend[idx]);
    }
}

// ---- kernel 4: main scan with correct init, emit y, packed f32x2 ------------
__global__ void __launch_bounds__(128, 6) scan_main_kernel(const float* __restrict__ u,
                                                           const float* __restrict__ A,
                                                           float* __restrict__ y) {
    __shared__ float ds[CL];
    __shared__ __align__(16) float Bs[CL*NST];
    __shared__ __align__(16) float Cs[CL*NST];
    __shared__ __align__(16) float Uss[HCL*128];   // half tile
    int t = threadIdx.x;
    int b = blockIdx.z, c = blockIdx.y;
    int d0 = blockIdx.x * 128;
    int d = d0 + t;
    int pos0 = b*SEQL + c*CL;

    if (t < CL) ds[t] = g_delta[pos0 + t];
#pragma unroll
    for (int i = t; i < CL*NST/4; i += 128) {
        *(float4*)(Bs + i*4) = *(const float4*)(g_Bt + (size_t)pos0*NST + i*4);
        *(float4*)(Cs + i*4) = *(const float4*)(g_Ct + (size_t)pos0*NST + i*4);
    }

    float A2[NST];
#pragma unroll
    for (int k = 0; k < 4; k++) {
        float4 a4 = *(const float4*)(A + d*NST + k*4);
        A2[k*4+0] = a4.x*LOG2E; A2[k*4+1] = a4.y*LOG2E;
        A2[k*4+2] = a4.z*LOG2E; A2[k*4+3] = a4.w*LOG2E;
    }
    u64 xp[8];
    const ulonglong2* xi = (const ulonglong2*)(g_xinit + (((size_t)b*DIM + d)*NCH + c)*NST);
#pragma unroll
    for (int q = 0; q < 4; q++) {
        ulonglong2 v = xi[q];
        xp[q*2] = v.x; xp[q*2+1] = v.y;
    }

    float* yp = y + (size_t)pos0*DIM + d;
#pragma unroll
    for (int h = 0; h < 2; h++) {
#pragma unroll
        for (int i = t; i < HCL*32; i += 128) {
            int row = i >> 5, col = i & 31;
            *(float4*)(Uss + row*128 + col*4) =
                *(const float4*)(u + (size_t)(pos0 + h*HCL + row)*DIM + d0 + col*4);
        }
        __syncthreads();
#pragma unroll 4
        for (int ll = 0; ll < HCL; ll++) {
            int l = h*HCL + ll;
            float dl = ds[l];
            float du = dl * Uss[ll*128 + t];
            u64 dup = pack2(du, du);
            const ulonglong2* bp = (const ulonglong2*)(Bs + l*NST);
            const ulonglong2* cp = (const ulonglong2*)(Cs + l*NST);
            u64 accp = 0ull;
#pragma unroll
            for (int k = 0; k < 4; k++) {
                float e0 = ex2f(dl*A2[k*4+0]);
                float e1 = ex2f(dl*A2[k*4+1]);
                float e2 = ex2f(dl*A2[k*4+2]);
                float e3 = ex2f(dl*A2[k*4+3]);
                u64 a01 = pack2(e0, e1), a23 = pack2(e2, e3);
                ulonglong2 bv = bp[k];
                ulonglong2 cv = cp[k];
                xp[k*2+0] = fma2(a01, xp[k*2+0], mul2(dup, bv.x));
                xp[k*2+1] = fma2(a23, xp[k*2+1], mul2(dup, bv.y));
                accp = fma2(xp[k*2+0], cv.x, accp);
                accp = fma2(xp[k*2+1], cv.y, accp);
            }
            float2 af = unpack2(accp);
            yp[(size_t)l*DIM] = af.x + af.y;
        }
        __syncthreads();
    }
}

extern "C" void kernel_launch(void* const* d_in, const int* in_sizes, int n_in,
                              void* d_out, int out_size) {
    const float* u       = (const float*)d_in[0];
    const float* A       = (const float*)d_in[1];
    const float* W_B     = (const float*)d_in[2];
    const float* W_C     = (const float*)d_in[3];
    const float* q_delta = (const float*)d_in[4];
    const float* p_delta = (const float*)d_in[5];
    float* y = (float*)d_out;

    proj_kernel<<<BL/TL, 128>>>(u, W_B, W_C, q_delta, p_delta);
    scan_init_kernel<<<dim3(DIM/128, NCH, BATCH), 128>>>(u, A);
    chain_kernel<<<(BATCH*DIM*NST)/256, 256>>>(A);
    scan_main_kernel<<<dim3(DIM/128, NCH, BATCH), 128>>>(u, A, y);
}

// round 13
// speedup vs baseline: 1.1102x; 1.1102x over previous
#include <cuda_runtime.h>
#include <math.h>

#define BATCH 4
#define SEQL  2048
#define DIM   768
#define NST   16
#define BL    (BATCH*SEQL)
#define NCH   32
#define CL    (SEQL/NCH)   // 64

#define TL 64              // proj tile == chunk
#define KC 32
#define LOG2E 1.4426950408889634f

typedef unsigned long long u64;

// scratch (static device globals — no runtime allocation)
__device__ float g_delta[BL];
__device__ float g_sdelta[BATCH*NCH];
__device__ float g_Bt[BL*NST];   // [pos][n]
__device__ float g_Ct[BL*NST];   // [pos][n]
__device__ float g_xend [BATCH*DIM*NCH*NST];
__device__ float g_xinit[BATCH*DIM*NCH*NST];

__device__ __forceinline__ float ex2f(float x) {
    float y;
    asm("ex2.approx.ftz.f32 %0, %1;" : "=f"(y) : "f"(x));
    return y;
}
__device__ __forceinline__ u64 pack2(float lo, float hi) {
    u64 r; asm("mov.b64 %0, {%1, %2};" : "=l"(r) : "f"(lo), "f"(hi)); return r;
}
__device__ __forceinline__ float2 unpack2(u64 v) {
    float2 f; asm("mov.b64 {%0, %1}, %2;" : "=f"(f.x), "=f"(f.y) : "l"(v)); return f;
}
__device__ __forceinline__ u64 fma2(u64 a, u64 b, u64 c) {
    u64 r; asm("fma.rn.f32x2 %0, %1, %2, %3;" : "=l"(r) : "l"(a), "l"(b), "l"(c)); return r;
}
__device__ __forceinline__ u64 mul2(u64 a, u64 b) {
    u64 r; asm("mul.rn.f32x2 %0, %1, %2;" : "=l"(r) : "l"(a), "l"(b)); return r;
}

// ---- kernel 1: proj + fused delta/softplus + chunk delta-sums ---------------
__global__ void proj_kernel(const float* __restrict__ u,
                            const float* __restrict__ W_B,
                            const float* __restrict__ W_C,
                            const float* __restrict__ q_delta,
                            const float* __restrict__ p_delta) {
    __shared__ __align__(16) float Us[KC*68];
    __shared__ __align__(16) float Ws[KC*36];
    __shared__ __align__(16) float Bo[TL*NST];
    __shared__ __align__(16) float Co[TL*NST];
    int t  = threadIdx.x;       // 128 threads
    int tx = t & 15;
    int ty = t >> 4;
    int blb = blockIdx.x * TL;

    float acc[4][4];
    float dacc[4] = {0.f, 0.f, 0.f, 0.f};
#pragma unroll
    for (int a = 0; a < 4; a++)
#pragma unroll
        for (int c = 0; c < 4; c++) acc[a][c] = 0.f;

    for (int dc = 0; dc < DIM; dc += KC) {
#pragma unroll
        for (int it = 0; it < (TL*KC)/128; it++) {
            int idx = t + it*128;
            int k = idx & 31, p = idx >> 5;
            Us[k*68 + p] = u[(size_t)(blb + p)*DIM + dc + k];
        }
#pragma unroll
        for (int it = 0; it < (32*KC)/128; it++) {
            int idx = t + it*128;
            int k = idx & 31, j = idx >> 5;
            const float* wr = (j < 16) ? (W_B + j*DIM) : (W_C + (j-16)*DIM);
            Ws[k*36 + j] = wr[dc + k];
        }
        if (t < 32) Ws[t*36 + 32] = q_delta[dc + t];
        __syncthreads();
#pragma unroll
        for (int k = 0; k < KC; k++) {
            float4 u4 = *(const float4*)(Us + k*68 + tx*4);
            float4 w4 = *(const float4*)(Ws + k*36 + ty*4);
            float us[4] = {u4.x, u4.y, u4.z, u4.w};
            float ws4[4] = {w4.x, w4.y, w4.z, w4.w};
#pragma unroll
            for (int a = 0; a < 4; a++)
#pragma unroll
                for (int c = 0; c < 4; c++)
                    acc[a][c] = fmaf(ws4[a], us[c], acc[a][c]);
            if (ty == 0) {
                float qk = Ws[k*36 + 32];
#pragma unroll
                for (int c = 0; c < 4; c++)
                    dacc[c] = fmaf(qk, us[c], dacc[c]);
            }
        }
        __syncthreads();
    }
    if (ty == 0) {
        float p0 = p_delta[0];
        float s = 0.f;
#pragma unroll
        for (int c = 0; c < 4; c++) {
            float z = dacc[c] + p0;
            float sp = (z > 20.f) ? z : log1pf(__expf(z));
            g_delta[blb + tx*4 + c] = sp;
            s += sp;
        }
#pragma unroll
        for (int o = 8; o; o >>= 1) s += __shfl_xor_sync(0xffffu, s, o);
        if (tx == 0) g_sdelta[blockIdx.x] = s;
    }
#pragma unroll
    for (int a = 0; a < 4; a++) {
        int j = ty*4 + a;
        float* o = (j < 16) ? Bo : Co;
        int jj = j & 15;
#pragma unroll
        for (int c = 0; c < 4; c++)
            o[(tx*4 + c)*NST + jj] = acc[a][c];
    }
    __syncthreads();
#pragma unroll
    for (int it = 0; it < (TL*NST)/(128*4); it++) {
        int i = (t + it*128)*4;
        *(float4*)(g_Bt + (size_t)blb*NST + i) = *(const float4*)(Bo + i);
        *(float4*)(g_Ct + (size_t)blb*NST + i) = *(const float4*)(Co + i);
    }
}

// ---- kernel 2: local chunk scans (x0 = 0) -> x_end (R8 verbatim, scalar) ----
__global__ void __launch_bounds__(128, 5) scan_init_kernel(const float* __restrict__ u,
                                                           const float* __restrict__ A) {
    __shared__ float ds[CL];
    __shared__ __align__(16) float Bs[CL*NST];
    __shared__ __align__(16) float Uss[CL*128];
    int t = threadIdx.x;
    int b = blockIdx.z, c = blockIdx.y;
    int d0 = blockIdx.x * 128;
    int d = d0 + t;
    int pos0 = b*SEQL + c*CL;

    if (t < CL) ds[t] = g_delta[pos0 + t];
#pragma unroll
    for (int i = t; i < CL*NST/4; i += 128)
        *(float4*)(Bs + i*4) = *(const float4*)(g_Bt + (size_t)pos0*NST + i*4);
#pragma unroll
    for (int i = t; i < CL*32; i += 128) {
        int row = i >> 5, col = i & 31;
        *(float4*)(Uss + row*128 + col*4) =
            *(const float4*)(u + (size_t)(pos0 + row)*DIM + d0 + col*4);
    }
    __syncthreads();

    float A2[NST];
#pragma unroll
    for (int k = 0; k < 4; k++) {
        float4 a4 = *(const float4*)(A + d*NST + k*4);
        A2[k*4+0] = a4.x*LOG2E; A2[k*4+1] = a4.y*LOG2E;
        A2[k*4+2] = a4.z*LOG2E; A2[k*4+3] = a4.w*LOG2E;
    }
    float x[NST];
#pragma unroll
    for (int k = 0; k < NST; k++) x[k] = 0.f;

#pragma unroll 4
    for (int l = 0; l < CL; l++) {
        float dl = ds[l];
        float du = dl * Uss[l*128 + t];
        const float4* bp = (const float4*)(Bs + l*NST);
#pragma unroll
        for (int k = 0; k < 4; k++) {
            float4 b4 = bp[k];
            x[k*4+0] = fmaf(ex2f(dl*A2[k*4+0]), x[k*4+0], du*b4.x);
            x[k*4+1] = fmaf(ex2f(dl*A2[k*4+1]), x[k*4+1], du*b4.y);
            x[k*4+2] = fmaf(ex2f(dl*A2[k*4+2]), x[k*4+2], du*b4.z);
            x[k*4+3] = fmaf(ex2f(dl*A2[k*4+3]), x[k*4+3], du*b4.w);
        }
    }
    float* xe = g_xend + (((size_t)b*DIM + d)*NCH + c)*NST;
#pragma unroll
    for (int k = 0; k < 4; k++)
        *(float4*)(xe + k*4) = make_float4(x[k*4], x[k*4+1], x[k*4+2], x[k*4+3]);
}

// ---- kernel 3: serial chain over chunks -> x_init ---------------------------
__global__ void chain_kernel(const float* __restrict__ A) {
    int t = blockIdx.x * blockDim.x + threadIdx.x;
    int n = t & 15;
    int bd = t >> 4;
    int b = bd / DIM;
    int d = bd - b*DIM;
    float A2 = A[d*NST + n] * LOG2E;
    float x = 0.f;
#pragma unroll
    for (int c = 0; c < NCH; c++) {
        size_t idx = ((size_t)bd*NCH + c)*NST + n;
        g_xinit[idx] = x;
        float P = ex2f(A2 * g_sdelta[b*NCH + c]);
        x = fmaf(P, x, g_xend[idx]);
    }
}

// ---- kernel 4: main scan (R8 structure, f32x2 inner math) -------------------
__global__ void __launch_bounds__(128, 5) scan_main_kernel(const float* __restrict__ u,
                                                           const float* __restrict__ A,
                                                           float* __restrict__ y) {
    __shared__ float ds[CL];
    __shared__ __align__(16) float Bs[CL*NST];
    __shared__ __align__(16) float Cs[CL*NST];
    __shared__ __align__(16) float Uss[CL*128];
    int t = threadIdx.x;
    int b = blockIdx.z, c = blockIdx.y;
    int d0 = blockIdx.x * 128;
    int d = d0 + t;
    int pos0 = b*SEQL + c*CL;

    if (t < CL) ds[t] = g_delta[pos0 + t];
#pragma unroll
    for (int i = t; i < CL*NST/4; i += 128) {
        *(float4*)(Bs + i*4) = *(const float4*)(g_Bt + (size_t)pos0*NST + i*4);
        *(float4*)(Cs + i*4) = *(const float4*)(g_Ct + (size_t)pos0*NST + i*4);
    }
#pragma unroll
    for (int i = t; i < CL*32; i += 128) {
        int row = i >> 5, col = i & 31;
        *(float4*)(Uss + row*128 + col*4) =
            *(const float4*)(u + (size_t)(pos0 + row)*DIM + d0 + col*4);
    }
    __syncthreads();

    float A2[NST];
#pragma unroll
    for (int k = 0; k < 4; k++) {
        float4 a4 = *(const float4*)(A + d*NST + k*4);
        A2[k*4+0] = a4.x*LOG2E; A2[k*4+1] = a4.y*LOG2E;
        A2[k*4+2] = a4.z*LOG2E; A2[k*4+3] = a4.w*LOG2E;
    }
    u64 xp[8];
    const ulonglong2* xi = (const ulonglong2*)(g_xinit + (((size_t)b*DIM + d)*NCH + c)*NST);
#pragma unroll
    for (int q = 0; q < 4; q++) {
        ulonglong2 v = xi[q];
        xp[q*2] = v.x; xp[q*2+1] = v.y;
    }

    float* yp = y + (size_t)pos0*DIM + d;
#pragma unroll 4
    for (int l = 0; l < CL; l++) {
        float dl = ds[l];
        float du = dl * Uss[l*128 + t];
        u64 dup = pack2(du, du);
        const ulonglong2* bp = (const ulonglong2*)(Bs + l*NST);
        const ulonglong2* cp = (const ulonglong2*)(Cs + l*NST);
        u64 accp = 0ull;
#pragma unroll
        for (int k = 0; k < 4; k++) {
            float e0 = ex2f(dl*A2[k*4+0]);
            float e1 = ex2f(dl*A2[k*4+1]);
            float e2 = ex2f(dl*A2[k*4+2]);
            float e3 = ex2f(dl*A2[k*4+3]);
            u64 a01 = pack2(e0, e1), a23 = pack2(e2, e3);
            ulonglong2 bv = bp[k];
            ulonglong2 cv = cp[k];
            xp[k*2+0] = fma2(a01, xp[k*2+0], mul2(dup, bv.x));
            xp[k*2+1] = fma2(a23, xp[k*2+1], mul2(dup, bv.y));
            accp = fma2(xp[k*2+0], cv.x, accp);
            accp = fma2(xp[k*2+1], cv.y, accp);
        }
        float2 af = unpack2(accp);
        yp[(size_t)l*DIM] = af.x + af.y;
    }
}

extern "C" void kernel_launch(void* const* d_in, const int* in_sizes, int n_in,
                              void* d_out, int out_size) {
    const float* u       = (const float*)d_in[0];
    const float* A       = (const float*)d_in[1];
    const float* W_B     = (const float*)d_in[2];
    const float* W_C     = (const float*)d_in[3];
    const float* q_delta = (const float*)d_in[4];
    const float* p_delta = (const float*)d_in[5];
    float* y = (float*)d_out;

    proj_kernel<<<BL/TL, 128>>>(u, W_B, W_C, q_delta, p_delta);
    scan_init_kernel<<<dim3(DIM/128, NCH, BATCH), 128>>>(u, A);
    chain_kernel<<<(BATCH*DIM*NST)/256, 256>>>(A);
    scan_main_kernel<<<dim3(DIM/128, NCH, BATCH), 128>>>(u, A, y);
}